// round 2
// baseline (speedup 1.0000x reference)
#include <cuda_runtime.h>
#include <cstdint>

#define NB      256          // N_RES * EXPR flattened rows
#define NC      1025         // coeffs per row
#define NF      128          // frames
#define HOP     1024
#define NSAMP   131072

// Scratch (allowed: __device__ globals, no runtime alloc)
__device__ float2 g_spec[33587200];            // NB*NF*NC complex spectrum
__device__ float  g_frames[67108864];          // NB*NF*2048 time-domain frames

// ---------------------------------------------------------------------------
// Threefry-2x32 (20 rounds), JAX partitionable counter mode: key=(0,42),
// x=(hi32(i)=0, lo32(i)=i), 32-bit output = v0 ^ v1.
// ---------------------------------------------------------------------------
__device__ __forceinline__ uint32_t threefry_xor(uint32_t x0, uint32_t x1) {
    const uint32_t ks0 = 0u, ks1 = 42u;
    const uint32_t ks2 = ks0 ^ ks1 ^ 0x1BD11BDAu;
    x0 += ks0; x1 += ks1;
#define TF_R(r) { x0 += x1; x1 = __funnelshift_l(x1, x1, (r)); x1 ^= x0; }
    TF_R(13) TF_R(15) TF_R(26) TF_R(6)
    x0 += ks1; x1 += ks2 + 1u;
    TF_R(17) TF_R(29) TF_R(16) TF_R(24)
    x0 += ks2; x1 += ks0 + 2u;
    TF_R(13) TF_R(15) TF_R(26) TF_R(6)
    x0 += ks0; x1 += ks1 + 3u;
    TF_R(17) TF_R(29) TF_R(16) TF_R(24)
    x0 += ks1; x1 += ks2 + 4u;
    TF_R(13) TF_R(15) TF_R(26) TF_R(6)
    x0 += ks2; x1 += ks0 + 5u;
#undef TF_R
    return x0 ^ x1;
}

// ---------------------------------------------------------------------------
// Kernel 1: per (row b, bin k) — params -> coeffs/mags/phase; sequential
// cumsum over 128 frames with on-the-fly Threefry noise; write complex spec.
// ---------------------------------------------------------------------------
__global__ void __launch_bounds__(256) spec_kernel(
    const float* __restrict__ amp,   const float* __restrict__ phase,
    const float* __restrict__ decay, const float* __restrict__ dith)
{
    int gid = blockIdx.x * 256 + threadIdx.x;
    if (gid >= NB * NC) return;
    int b = gid / NC;
    int k = gid - b * NC;
    // inputs are (N_RES, NC, EXPR); flattened row b = r*4+e
    int pidx = (((b >> 2) * NC + k) << 2) + (b & 3);

    float a  = amp[pidx];
    float ph = phase[pidx];
    float dc = decay[pidx];
    float dt = dith[pidx];

    float sig = 1.0f / (1.0f + expf(-dc));
    float c   = 0.5f + (sig * 0.5f) * 0.99f;      // BASE_RES + sigmoid*span*factor
    float m   = a * a;                             // start_mags
    float sp  = tanhf(ph) * 3.14159274101257324f;  // tanh(phase)*pi (fp32 pi)
    float d   = tanhf(dt);                         // dither

    uint32_t idx = (uint32_t)(b * NF) * (uint32_t)NC + (uint32_t)k;  // linear noise index, t=0
    float acc = 0.0f;
    float2* __restrict__ outp = g_spec + idx;

    #pragma unroll 4
    for (int t = 0; t < NF; t++) {
        uint32_t bits = threefry_xor(0u, idx);
        float u  = __uint_as_float((bits >> 9) | 0x3f800000u) - 1.0f;  // [0,1)
        float nz = fmaxf(-1.0f, fmaf(u, 2.0f, -1.0f));                 // [-1,1)
        acc += fmaf(d, nz, sp);      // cumsum of phase_step (fp32, unwrapped)
        m   *= c;                    // start_mags * c^t  (t = 1..128)

        // accurate 2-term range reduction, then HW sincos
        float kq  = rintf(acc * 0.15915494309189535f);
        float red = fmaf(kq, -6.2831854820251465f, acc);
        red       = fmaf(kq,  1.7484555e-07f, red);
        float sn, cs;
        __sincosf(red, &sn, &cs);

        *outp = make_float2(m * cs, m * sn);
        outp += NC;
        idx  += NC;
    }
}

// ---------------------------------------------------------------------------
// Kernel 2: per frame — irfft(1025 -> 2048 real) via 1024-pt complex inverse
// FFT (radix-4 Stockham, padded shared memory, conflict-free).
// ---------------------------------------------------------------------------
__device__ __forceinline__ float2 cadd(float2 a, float2 b){ return make_float2(a.x+b.x, a.y+b.y); }
__device__ __forceinline__ float2 csub(float2 a, float2 b){ return make_float2(a.x-b.x, a.y-b.y); }
__device__ __forceinline__ float2 cmul(float2 a, float2 b){
    return make_float2(a.x*b.x - a.y*b.y, a.x*b.y + a.y*b.x);
}
#define PADI(i) ((i) + ((i) >> 5))

__global__ void __launch_bounds__(256) ifft_kernel()
{
    __shared__ float2 bufA[1056];
    __shared__ float2 bufB[1056];

    const int f   = blockIdx.x;              // frame id: b*128 + t
    const int tid = threadIdx.x;
    const float2* __restrict__ X = g_spec + (size_t)f * NC;

    // Build Z[k] = A[k] + i*B[k], folded 1/2048 normalization.
    // A = (X[k] + conj(X[1024-k]))/2,  B = e^{+i*pi*k/1024} * (X[k] - conj(X[1024-k]))/2
    const float inv = 1.0f / 2048.0f;
    #pragma unroll
    for (int i = 0; i < 4; i++) {
        int k = tid + i * 256;
        float2 Xk = X[k];
        float2 Xm = X[1024 - k];
        if (k == 0) { Xk.y = 0.0f; Xm.y = 0.0f; }   // c2r ignores imag of bins 0, N/2
        float Ax = (Xk.x + Xm.x) * inv;
        float Ay = (Xk.y - Xm.y) * inv;
        float Dx = (Xk.x - Xm.x) * inv;
        float Dy = (Xk.y + Xm.y) * inv;
        float sw, cw;
        __sincosf((float)k * (3.14159265358979f / 1024.0f), &sw, &cw);
        float Bx = Dx * cw - Dy * sw;
        float By = Dx * sw + Dy * cw;
        bufA[PADI(k)] = make_float2(Ax - By, Ay + Bx);
    }
    __syncthreads();

    // 5 radix-4 Stockham stages, inverse (+i) DFT of length 1024.
    float2* src = bufA;
    float2* dst = bufB;
    #pragma unroll
    for (int stage = 0; stage < 5; stage++) {
        const int ls = 2 * stage;          // log2(s): s = 1,4,16,64,256
        const int s_ = 1 << ls;
        const int n  = 1024 >> ls;         // 1024,256,64,16,4
        const int u  = tid;
        const int q  = u & (s_ - 1);
        const int p  = u >> ls;

        float2 a = src[PADI(u)];
        float2 b = src[PADI(u + 256)];     // s*m == 256 at every stage
        float2 c = src[PADI(u + 512)];
        float2 d = src[PADI(u + 768)];

        float2 apc = cadd(a, c), amc = csub(a, c);
        float2 bpd = cadd(b, d), bmd = csub(b, d);
        float2 t0 = cadd(apc, bpd);
        float2 t2 = csub(apc, bpd);
        float2 t1 = make_float2(amc.x - bmd.y, amc.y + bmd.x);  // (a-c) + i(b-d)
        float2 t3 = make_float2(amc.x + bmd.y, amc.y - bmd.x);  // (a-c) - i(b-d)

        float ang = (float)p * (6.283185307179586f / (float)n);
        float sn, cs;
        __sincosf(ang, &sn, &cs);
        float2 w1 = make_float2(cs, sn);
        float2 w2 = cmul(w1, w1);
        float2 w3 = cmul(w2, w1);
        t1 = cmul(t1, w1);
        t2 = cmul(t2, w2);
        t3 = cmul(t3, w3);

        int wb = q + (p << (ls + 2));      // q + s*4p
        dst[PADI(wb)]          = t0;
        dst[PADI(wb + s_)]     = t1;
        dst[PADI(wb + 2*s_)]   = t2;
        dst[PADI(wb + 3*s_)]   = t3;
        __syncthreads();
        float2* tmp = src; src = dst; dst = tmp;
    }

    // z[m] = x[2m] + i*x[2m+1] — store frame (contiguous pairs as float2)
    float2* __restrict__ fr = reinterpret_cast<float2*>(g_frames + (size_t)f * 2048);
    #pragma unroll
    for (int i = 0; i < 4; i++) {
        int mm = tid + i * 256;
        fr[mm] = src[PADI(mm)];
    }
}

// ---------------------------------------------------------------------------
// Kernel 3: overlap-add gather. out[b,n] = frames[b,t,j] + frames[b,t-1,j+1024]
// with t = n>>10, j = n&1023. Every frame element read exactly once. float4.
// ---------------------------------------------------------------------------
__global__ void __launch_bounds__(256) ola_kernel(float4* __restrict__ out)
{
    int gid = blockIdx.x * 256 + threadIdx.x;      // over 8388608 float4s
    int b  = gid >> 15;                            // 32768 float4 per row
    int n4 = gid & 32767;
    int t  = n4 >> 8;                              // 256 float4 per hop
    int j4 = n4 & 255;

    const float4* __restrict__ frp = reinterpret_cast<const float4*>(g_frames);
    float4 v = frp[(b * NF + t) * 512 + j4];       // first half of frame t
    if (t > 0) {
        float4 w = frp[(b * NF + t - 1) * 512 + 256 + j4];  // second half of frame t-1
        v.x += w.x; v.y += w.y; v.z += w.z; v.w += w.w;
    }
    out[gid] = v;
}

// ---------------------------------------------------------------------------
extern "C" void kernel_launch(void* const* d_in, const int* in_sizes, int n_in,
                              void* d_out, int out_size)
{
    const float* amp   = (const float*)d_in[0];
    const float* phase = (const float*)d_in[1];
    const float* decay = (const float*)d_in[2];
    const float* dith  = (const float*)d_in[3];
    float* out = (float*)d_out;

    spec_kernel<<<(NB * NC + 255) / 256, 256>>>(amp, phase, decay, dith);
    ifft_kernel<<<NB * NF, 256>>>();
    ola_kernel<<<(NB * NSAMP / 4) / 256, 256>>>((float4*)out);
}

// round 3
// speedup vs baseline: 1.2013x; 1.2013x over previous
#include <cuda_runtime.h>
#include <cuda_fp16.h>
#include <cstdint>

#define NB      256          // N_RES * EXPR flattened rows
#define NC      1025         // coeffs per row
#define NF      128          // frames
#define HOP     1024
#define NSAMP   131072

// Scratch (allowed: __device__ globals, no runtime alloc)
__device__ __half2 g_spec[33587200];     // NB*NF*NC complex spectrum (fp16)  134MB
__device__ __half2 g_frames[33554432];   // NB*NF*1024 packed frame pairs     134MB

// ---------------------------------------------------------------------------
// Threefry-2x32 (20 rounds), JAX partitionable counter mode: key=(0,42),
// x=(0, i), 32-bit output = v0 ^ v1.   (bit-verified in round 2)
// ---------------------------------------------------------------------------
__device__ __forceinline__ uint32_t threefry_xor(uint32_t x0, uint32_t x1) {
    const uint32_t ks0 = 0u, ks1 = 42u;
    const uint32_t ks2 = ks0 ^ ks1 ^ 0x1BD11BDAu;
    x0 += ks0; x1 += ks1;
#define TF_R(r) { x0 += x1; x1 = __funnelshift_l(x1, x1, (r)); x1 ^= x0; }
    TF_R(13) TF_R(15) TF_R(26) TF_R(6)
    x0 += ks1; x1 += ks2 + 1u;
    TF_R(17) TF_R(29) TF_R(16) TF_R(24)
    x0 += ks2; x1 += ks0 + 2u;
    TF_R(13) TF_R(15) TF_R(26) TF_R(6)
    x0 += ks0; x1 += ks1 + 3u;
    TF_R(17) TF_R(29) TF_R(16) TF_R(24)
    x0 += ks1; x1 += ks2 + 4u;
    TF_R(13) TF_R(15) TF_R(26) TF_R(6)
    x0 += ks2; x1 += ks0 + 5u;
#undef TF_R
    return x0 ^ x1;
}

// ---------------------------------------------------------------------------
// Kernel 1: per (row b, bin k) — params -> coeffs/mags/phase; sequential
// cumsum over 128 frames with on-the-fly Threefry noise; write fp16 spectrum.
// ---------------------------------------------------------------------------
__global__ void __launch_bounds__(256) spec_kernel(
    const float* __restrict__ amp,   const float* __restrict__ phase,
    const float* __restrict__ decay, const float* __restrict__ dith)
{
    int gid = blockIdx.x * 256 + threadIdx.x;
    if (gid >= NB * NC) return;
    int b = gid / NC;
    int k = gid - b * NC;
    // inputs are (N_RES, NC, EXPR); flattened row b = r*4+e
    int pidx = (((b >> 2) * NC + k) << 2) + (b & 3);

    float a  = amp[pidx];
    float ph = phase[pidx];
    float dc = decay[pidx];
    float dt = dith[pidx];

    float sig = 1.0f / (1.0f + expf(-dc));
    float c   = 0.5f + (sig * 0.5f) * 0.99f;       // BASE_RES + sigmoid*span*factor
    float m   = a * a;                              // start_mags
    float sp  = tanhf(ph) * 3.14159274101257324f;   // tanh(phase)*pi
    float d   = tanhf(dt);                          // dither

    uint32_t idx = (uint32_t)(b * NF) * (uint32_t)NC + (uint32_t)k;
    float acc = 0.0f;
    __half2* __restrict__ outp = g_spec + idx;

    #pragma unroll 4
    for (int t = 0; t < NF; t++) {
        uint32_t bits = threefry_xor(0u, idx);
        float u  = __uint_as_float((bits >> 9) | 0x3f800000u) - 1.0f;  // [0,1)
        float nz = fmaxf(-1.0f, fmaf(u, 2.0f, -1.0f));                 // [-1,1)
        acc += fmaf(d, nz, sp);     // cumsum of phase_step
        m   *= c;                   // start_mags * c^t

        float kq  = rintf(acc * 0.15915494309189535f);
        float red = fmaf(kq, -6.2831854820251465f, acc);
        red       = fmaf(kq,  1.7484555e-07f, red);
        float sn, cs;
        __sincosf(red, &sn, &cs);

        *outp = __floats2half2_rn(m * cs, m * sn);
        outp += NC;
        idx  += NC;
    }
}

// ---------------------------------------------------------------------------
// Kernel 2: per frame — irfft(1025 -> 2048 real) via 1024-pt complex inverse
// FFT. Radix-4 Stockham; stages 0 and 4 fused into prologue/epilogue
// (register-resident), only 3 shared-memory exchange rounds.
// ---------------------------------------------------------------------------
__device__ __forceinline__ float2 cadd(float2 a, float2 b){ return make_float2(a.x+b.x, a.y+b.y); }
__device__ __forceinline__ float2 csub(float2 a, float2 b){ return make_float2(a.x-b.x, a.y-b.y); }
__device__ __forceinline__ float2 cmul(float2 a, float2 b){
    return make_float2(a.x*b.x - a.y*b.y, a.x*b.y + a.y*b.x);
}
#define PADI(i) ((i) + ((i) >> 5))

__device__ __forceinline__ void radix4_inv(float2 a, float2 b, float2 c, float2 d,
                                           float2& t0, float2& t1, float2& t2, float2& t3)
{
    float2 apc = cadd(a, c), amc = csub(a, c);
    float2 bpd = cadd(b, d), bmd = csub(b, d);
    t0 = cadd(apc, bpd);
    t2 = csub(apc, bpd);
    t1 = make_float2(amc.x - bmd.y, amc.y + bmd.x);  // (a-c) + i(b-d)
    t3 = make_float2(amc.x + bmd.y, amc.y - bmd.x);  // (a-c) - i(b-d)
}

__global__ void __launch_bounds__(256) ifft_kernel()
{
    __shared__ float2 bufA[1056];
    __shared__ float2 bufB[1056];

    const int f   = blockIdx.x;              // frame id: b*128 + t
    const int tid = threadIdx.x;
    const __half2* __restrict__ X = g_spec + (size_t)f * NC;

    // Hermitian fold -> Z[k] = A + iB (1/2048 normalization folded in)
    float2 z[4];
    const float inv = 1.0f / 2048.0f;
    #pragma unroll
    for (int i = 0; i < 4; i++) {
        int k = tid + i * 256;
        float2 Xk = __half22float2(X[k]);
        float2 Xm = __half22float2(X[1024 - k]);
        if (k == 0) { Xk.y = 0.0f; Xm.y = 0.0f; }   // c2r ignores imag of bins 0, N/2
        float Ax = (Xk.x + Xm.x) * inv;
        float Ay = (Xk.y - Xm.y) * inv;
        float Dx = (Xk.x - Xm.x) * inv;
        float Dy = (Xk.y + Xm.y) * inv;
        float sw, cw;
        __sincosf((float)k * (3.14159265358979f / 1024.0f), &sw, &cw);
        float Bx = Dx * cw - Dy * sw;
        float By = Dx * sw + Dy * cw;
        z[i] = make_float2(Ax - By, Ay + Bx);
    }

    // Stage 0 (s=1) fully in registers: inputs are exactly z[0..3] (stride 256).
    {
        float2 t0, t1, t2, t3;
        radix4_inv(z[0], z[1], z[2], z[3], t0, t1, t2, t3);
        float ang = (float)tid * (6.283185307179586f / 1024.0f);
        float sn, cs;
        __sincosf(ang, &sn, &cs);
        float2 w1 = make_float2(cs, sn);
        float2 w2 = cmul(w1, w1);
        float2 w3 = cmul(w2, w1);
        int wb = tid << 2;
        bufA[PADI(wb)]     = t0;
        bufA[PADI(wb + 1)] = cmul(t1, w1);
        bufA[PADI(wb + 2)] = cmul(t2, w2);
        bufA[PADI(wb + 3)] = cmul(t3, w3);
    }
    __syncthreads();

    // Stages 1..3 via shared memory (s = 4, 16, 64)
    float2* src = bufA;
    float2* dst = bufB;
    #pragma unroll
    for (int stage = 1; stage < 4; stage++) {
        const int ls = 2 * stage;
        const int s_ = 1 << ls;
        const int n  = 1024 >> ls;
        const int u  = tid;
        const int q  = u & (s_ - 1);
        const int p  = u >> ls;

        float2 a = src[PADI(u)];
        float2 b = src[PADI(u + 256)];
        float2 c = src[PADI(u + 512)];
        float2 d = src[PADI(u + 768)];

        float2 t0, t1, t2, t3;
        radix4_inv(a, b, c, d, t0, t1, t2, t3);

        float ang = (float)p * (6.283185307179586f / (float)n);
        float sn, cs;
        __sincosf(ang, &sn, &cs);
        float2 w1 = make_float2(cs, sn);
        float2 w2 = cmul(w1, w1);
        float2 w3 = cmul(w2, w1);

        int wb = q + (p << (ls + 2));
        dst[PADI(wb)]        = t0;
        dst[PADI(wb + s_)]   = cmul(t1, w1);
        dst[PADI(wb + 2*s_)] = cmul(t2, w2);
        dst[PADI(wb + 3*s_)] = cmul(t3, w3);
        __syncthreads();
        float2* tmp = src; src = dst; dst = tmp;
    }

    // Stage 4 (s=256, p=0, twiddle=1) fused into epilogue: outputs land at
    // tid, tid+256, tid+512, tid+768 — store straight to global as fp16 pairs.
    {
        float2 a = src[PADI(tid)];
        float2 b = src[PADI(tid + 256)];
        float2 c = src[PADI(tid + 512)];
        float2 d = src[PADI(tid + 768)];
        float2 t0, t1, t2, t3;
        radix4_inv(a, b, c, d, t0, t1, t2, t3);

        __half2* __restrict__ fr = g_frames + (size_t)f * 1024;  // z[m]=(x[2m],x[2m+1])
        fr[tid]       = __floats2half2_rn(t0.x, t0.y);
        fr[tid + 256] = __floats2half2_rn(t1.x, t1.y);
        fr[tid + 512] = __floats2half2_rn(t2.x, t2.y);
        fr[tid + 768] = __floats2half2_rn(t3.x, t3.y);
    }
}

// ---------------------------------------------------------------------------
// Kernel 3: overlap-add gather, 8 samples per thread.
// out[b,n] = frames[b,t, n&1023] + frames[b,t-1, (n&1023)+1024],  t = n>>10.
// ---------------------------------------------------------------------------
__global__ void __launch_bounds__(256) ola_kernel(float4* __restrict__ out)
{
    int gid = blockIdx.x * 256 + threadIdx.x;   // 4,194,304 threads x 8 samples
    int b = gid >> 14;                          // 16384 groups per row
    int r = gid & 16383;
    int t = r >> 7;                             // 128 groups per hop
    int g = r & 127;

    const uint4* __restrict__ fr4 = reinterpret_cast<const uint4*>(g_frames);
    uint4 va = fr4[(b * NF + t) * 256 + g];     // frame t, first half (8 halves)
    __half2 ha[4];
    *reinterpret_cast<uint4*>(ha) = va;
    float2 f0 = __half22float2(ha[0]);
    float2 f1 = __half22float2(ha[1]);
    float2 f2 = __half22float2(ha[2]);
    float2 f3 = __half22float2(ha[3]);

    if (t > 0) {
        uint4 vb = fr4[(b * NF + t - 1) * 256 + 128 + g];  // frame t-1, second half
        __half2 hb[4];
        *reinterpret_cast<uint4*>(hb) = vb;
        float2 e0 = __half22float2(hb[0]);
        float2 e1 = __half22float2(hb[1]);
        float2 e2 = __half22float2(hb[2]);
        float2 e3 = __half22float2(hb[3]);
        f0.x += e0.x; f0.y += e0.y;
        f1.x += e1.x; f1.y += e1.y;
        f2.x += e2.x; f2.y += e2.y;
        f3.x += e3.x; f3.y += e3.y;
    }

    out[gid * 2]     = make_float4(f0.x, f0.y, f1.x, f1.y);
    out[gid * 2 + 1] = make_float4(f2.x, f2.y, f3.x, f3.y);
}

// ---------------------------------------------------------------------------
extern "C" void kernel_launch(void* const* d_in, const int* in_sizes, int n_in,
                              void* d_out, int out_size)
{
    const float* amp   = (const float*)d_in[0];
    const float* phase = (const float*)d_in[1];
    const float* decay = (const float*)d_in[2];
    const float* dith  = (const float*)d_in[3];
    float* out = (float*)d_out;

    spec_kernel<<<(NB * NC + 255) / 256, 256>>>(amp, phase, decay, dith);
    ifft_kernel<<<NB * NF, 256>>>();
    ola_kernel<<<(NB * NSAMP / 8 + 255) / 256, 256>>>((float4*)out);
}

// round 4
// speedup vs baseline: 1.3060x; 1.0871x over previous
#include <cuda_runtime.h>
#include <cuda_fp16.h>
#include <cstdint>

#define NB      256          // N_RES * EXPR flattened rows
#define NC      1025         // coeffs per row
#define NF      128          // frames
#define HOP     1024
#define NSAMP   131072
#define FPB     16           // frames per block in fused kernel
#define NCHUNK  (NF / FPB)   // 8

// Scratch (allowed: __device__ globals, no runtime alloc)
__device__ __half2 g_spec[33587200];     // NB*NF*NC complex spectrum (fp16) 134MB

// ---------------------------------------------------------------------------
// Threefry-2x32 (20 rounds), JAX partitionable counter mode: key=(0,42),
// x=(0, i), 32-bit output = v0 ^ v1.   (bit-verified in round 2)
// ---------------------------------------------------------------------------
__device__ __forceinline__ uint32_t threefry_xor(uint32_t x0, uint32_t x1) {
    const uint32_t ks0 = 0u, ks1 = 42u;
    const uint32_t ks2 = ks0 ^ ks1 ^ 0x1BD11BDAu;
    x0 += ks0; x1 += ks1;
#define TF_R(r) { x0 += x1; x1 = __funnelshift_l(x1, x1, (r)); x1 ^= x0; }
    TF_R(13) TF_R(15) TF_R(26) TF_R(6)
    x0 += ks1; x1 += ks2 + 1u;
    TF_R(17) TF_R(29) TF_R(16) TF_R(24)
    x0 += ks2; x1 += ks0 + 2u;
    TF_R(13) TF_R(15) TF_R(26) TF_R(6)
    x0 += ks0; x1 += ks1 + 3u;
    TF_R(17) TF_R(29) TF_R(16) TF_R(24)
    x0 += ks1; x1 += ks2 + 4u;
    TF_R(13) TF_R(15) TF_R(26) TF_R(6)
    x0 += ks2; x1 += ks0 + 5u;
#undef TF_R
    return x0 ^ x1;
}

// ---------------------------------------------------------------------------
// Kernel 1: per (row b, bin k) — params -> coeffs/mags/phase; sequential
// cumsum over 128 frames with on-the-fly Threefry noise; write fp16 spectrum.
// ---------------------------------------------------------------------------
__global__ void __launch_bounds__(256) spec_kernel(
    const float* __restrict__ amp,   const float* __restrict__ phase,
    const float* __restrict__ decay, const float* __restrict__ dith)
{
    int gid = blockIdx.x * 256 + threadIdx.x;
    if (gid >= NB * NC) return;
    int b = gid / NC;
    int k = gid - b * NC;
    // inputs are (N_RES, NC, EXPR); flattened row b = r*4+e
    int pidx = (((b >> 2) * NC + k) << 2) + (b & 3);

    float a  = amp[pidx];
    float ph = phase[pidx];
    float dc = decay[pidx];
    float dt = dith[pidx];

    float sig = 1.0f / (1.0f + expf(-dc));
    float c   = 0.5f + (sig * 0.5f) * 0.99f;       // BASE_RES + sigmoid*span*factor
    float m   = a * a;                              // start_mags
    float sp  = tanhf(ph) * 3.14159274101257324f;   // tanh(phase)*pi
    float d   = tanhf(dt);                          // dither

    uint32_t idx = (uint32_t)(b * NF) * (uint32_t)NC + (uint32_t)k;
    float acc = 0.0f;
    __half2* __restrict__ outp = g_spec + idx;

    #pragma unroll 4
    for (int t = 0; t < NF; t++) {
        uint32_t bits = threefry_xor(0u, idx);
        float u  = __uint_as_float((bits >> 9) | 0x3f800000u) - 1.0f;  // [0,1)
        float nz = fmaxf(-1.0f, fmaf(u, 2.0f, -1.0f));                 // [-1,1)
        acc += fmaf(d, nz, sp);     // cumsum of phase_step
        m   *= c;                   // start_mags * c^t

        float kq  = rintf(acc * 0.15915494309189535f);
        float red = fmaf(kq, -6.2831854820251465f, acc);
        red       = fmaf(kq,  1.7484555e-07f, red);
        float sn, cs;
        __sincosf(red, &sn, &cs);

        *outp = __floats2half2_rn(m * cs, m * sn);
        outp += NC;
        idx  += NC;
    }
}

// ---------------------------------------------------------------------------
// Kernel 2 (fused irfft + overlap-add):
// Each block handles one row b and FPB consecutive frames. It runs the
// 1024-pt complex inverse FFT (radix-4 Stockham, stages 0 & 4 fused into
// prologue/epilogue) once per frame, sequentially. The OLA overlap
// (second half of the previous frame) is carried in 2 registers/thread
// because thread tid owns the SAME pair indices (tid, tid+256) in the
// first half of frame t and (tid+512, tid+768) in the second half of t-1.
// One warm-up FFT per chunk (except chunk 0) supplies the incoming overlap.
// All per-frame twiddles are tid-only -> hoisted out of the frame loop.
// ---------------------------------------------------------------------------
__device__ __forceinline__ float2 cadd(float2 a, float2 b){ return make_float2(a.x+b.x, a.y+b.y); }
__device__ __forceinline__ float2 csub(float2 a, float2 b){ return make_float2(a.x-b.x, a.y-b.y); }
__device__ __forceinline__ float2 cmul(float2 a, float2 b){
    return make_float2(a.x*b.x - a.y*b.y, a.x*b.y + a.y*b.x);
}
#define PADI(i) ((i) + ((i) >> 5))

__device__ __forceinline__ void radix4_inv(float2 a, float2 b, float2 c, float2 d,
                                           float2& t0, float2& t1, float2& t2, float2& t3)
{
    float2 apc = cadd(a, c), amc = csub(a, c);
    float2 bpd = cadd(b, d), bmd = csub(b, d);
    t0 = cadd(apc, bpd);
    t2 = csub(apc, bpd);
    t1 = make_float2(amc.x - bmd.y, amc.y + bmd.x);  // (a-c) + i(b-d)
    t3 = make_float2(amc.x + bmd.y, amc.y - bmd.x);  // (a-c) - i(b-d)
}

__global__ void __launch_bounds__(256) ifft_ola_kernel(float2* __restrict__ out2)
{
    __shared__ float2 bufA[1056];
    __shared__ float2 bufB[1056];

    const int tid     = threadIdx.x;
    const int b       = blockIdx.y;
    const int t_start = blockIdx.x * FPB;
    const int t_first = (blockIdx.x == 0) ? 0 : t_start - 1;

    // ---- hoisted, frame-invariant twiddles (tid-only) ----
    float2 fw[4];                               // fold twiddles e^{+i pi k /1024}, k=tid+i*256
    #pragma unroll
    for (int i = 0; i < 4; i++) {
        float sw, cw;
        __sincosf((float)(tid + i * 256) * (3.14159265358979f / 1024.0f), &sw, &cw);
        fw[i] = make_float2(cw, sw);
    }
    const float2 s0w1 = cmul(fw[0], fw[0]);     // e^{i 2pi tid/1024}
    float2 stw1[3];                             // stage-s (s=1..3) first twiddle
    #pragma unroll
    for (int s = 1; s < 4; s++) {
        int p = tid >> (2 * s);
        float n = (float)(1024 >> (2 * s));
        float sn, cs;
        __sincosf((float)p * (6.283185307179586f / n), &sn, &cs);
        stw1[s - 1] = make_float2(cs, sn);
    }

    float2 prev2 = make_float2(0.0f, 0.0f);     // carried second-half pairs of frame t-1
    float2 prev3 = make_float2(0.0f, 0.0f);

    for (int t = t_first; t < t_start + FPB; t++) {
        const __half2* __restrict__ X = g_spec + (size_t)(b * NF + t) * NC;

        // Hermitian fold -> Z[k] = A + iB (1/2048 normalization folded in)
        float2 z[4];
        const float inv = 1.0f / 2048.0f;
        #pragma unroll
        for (int i = 0; i < 4; i++) {
            int k = tid + i * 256;
            float2 Xk = __half22float2(X[k]);
            float2 Xm = __half22float2(X[1024 - k]);
            if (k == 0) { Xk.y = 0.0f; Xm.y = 0.0f; }   // c2r ignores imag of bins 0, N/2
            float Ax = (Xk.x + Xm.x) * inv;
            float Ay = (Xk.y - Xm.y) * inv;
            float Dx = (Xk.x - Xm.x) * inv;
            float Dy = (Xk.y + Xm.y) * inv;
            float Bx = Dx * fw[i].x - Dy * fw[i].y;
            float By = Dx * fw[i].y + Dy * fw[i].x;
            z[i] = make_float2(Ax - By, Ay + Bx);
        }

        // Stage 0 (s=1) in registers: inputs are exactly z[0..3] (stride 256).
        {
            float2 r0, r1, r2, r3;
            radix4_inv(z[0], z[1], z[2], z[3], r0, r1, r2, r3);
            float2 w2 = cmul(s0w1, s0w1);
            float2 w3 = cmul(w2, s0w1);
            int wb = tid << 2;
            bufA[PADI(wb)]     = r0;
            bufA[PADI(wb + 1)] = cmul(r1, s0w1);
            bufA[PADI(wb + 2)] = cmul(r2, w2);
            bufA[PADI(wb + 3)] = cmul(r3, w3);
        }
        __syncthreads();

        // Stages 1..3 via shared memory (s = 4, 16, 64)
        float2* src = bufA;
        float2* dst = bufB;
        #pragma unroll
        for (int stage = 1; stage < 4; stage++) {
            const int ls = 2 * stage;
            const int s_ = 1 << ls;
            const int q  = tid & (s_ - 1);
            const int p  = tid >> ls;

            float2 a = src[PADI(tid)];
            float2 bb = src[PADI(tid + 256)];
            float2 c = src[PADI(tid + 512)];
            float2 d = src[PADI(tid + 768)];

            float2 r0, r1, r2, r3;
            radix4_inv(a, bb, c, d, r0, r1, r2, r3);

            float2 w1 = stw1[stage - 1];
            float2 w2 = cmul(w1, w1);
            float2 w3 = cmul(w2, w1);

            int wb = q + (p << (ls + 2));
            dst[PADI(wb)]        = r0;
            dst[PADI(wb + s_)]   = cmul(r1, w1);
            dst[PADI(wb + 2*s_)] = cmul(r2, w2);
            dst[PADI(wb + 3*s_)] = cmul(r3, w3);
            __syncthreads();
            float2* tmp = src; src = dst; dst = tmp;
        }

        // Stage 4 (s=256, p=0, twiddle=1) fused epilogue + OLA output.
        // After 3 swaps, src == bufB.
        {
            float2 a = src[PADI(tid)];
            float2 bb = src[PADI(tid + 256)];
            float2 c = src[PADI(tid + 512)];
            float2 d = src[PADI(tid + 768)];
            float2 r0, r1, r2, r3;
            radix4_inv(a, bb, c, d, r0, r1, r2, r3);
            // r0,r1: pairs m=tid,tid+256 (samples 0..1023)  -> first half of frame t
            // r2,r3: pairs m=tid+512,tid+768 (samples 1024..2047) -> overlap for t+1

            if (t >= t_start) {
                int base = b * (NSAMP / 2) + t * 512;
                out2[base + tid]       = make_float2(r0.x + prev2.x, r0.y + prev2.y);
                out2[base + 256 + tid] = make_float2(r1.x + prev3.x, r1.y + prev3.y);
            }
            prev2 = r2;
            prev3 = r3;
        }
        // No extra sync needed: next prologue writes bufA, whose last reads
        // (stage 3) are already ordered by stage 3's trailing __syncthreads();
        // the epilogue's bufB reads are ordered before stage 1's bufB writes
        // by the sync after the next prologue.
    }
}

// ---------------------------------------------------------------------------
extern "C" void kernel_launch(void* const* d_in, const int* in_sizes, int n_in,
                              void* d_out, int out_size)
{
    const float* amp   = (const float*)d_in[0];
    const float* phase = (const float*)d_in[1];
    const float* decay = (const float*)d_in[2];
    const float* dith  = (const float*)d_in[3];
    float* out = (float*)d_out;

    spec_kernel<<<(NB * NC + 255) / 256, 256>>>(amp, phase, decay, dith);
    dim3 grid2(NCHUNK, NB);
    ifft_ola_kernel<<<grid2, 256>>>((float2*)out);
}